// round 3
// baseline (speedup 1.0000x reference)
#include <cuda_runtime.h>
#include <cuda_bf16.h>
#include <math.h>

#define B_N   8192
#define DIN   256
#define DE    128
#define NEX   16384
#define NDUR  64
#define GAMMA_N 3.6787944117144233e-06f   // exp(-1)/100000

// ---------------- device scratch (no runtime allocation allowed) ----------------
__device__ __align__(16) float g_phiT[DE * B_N];       // -2*phi, [DE][B]
__device__ __align__(16) float g_pn[B_N];              // ||phi||^2
__device__ __align__(16) float g_Et[DE * NEX];         // E^T, [DE][NEX]
__device__ __align__(16) float g_en[NEX];              // ||E||^2
__device__ __align__(16) float g_KM[NEX * NDUR];       // exemplar KM
__device__ __align__(16) float g_gbh[NDUR];            // gamma * baseline KM
__device__ __align__(16) float g_pnum[2 * B_N * NDUR]; // split partial numerators
__device__ __align__(16) float g_pden[2 * B_N];        // split partial denominators

// ---------------- helpers ----------------
__device__ __forceinline__ void cp_async16(void* smem, const void* gmem) {
    unsigned sa = (unsigned)__cvta_generic_to_shared(smem);
    asm volatile("cp.async.cg.shared.global [%0], [%1], 16;" :: "r"(sa), "l"(gmem));
}
#define CP_COMMIT() asm volatile("cp.async.commit_group;" ::: "memory")
#define CP_WAIT1()  asm volatile("cp.async.wait_group 1;" ::: "memory")
#define CP_WAIT0()  asm volatile("cp.async.wait_group 0;" ::: "memory")

// ---------------- kernel 1: phiT = -2*(x@W + b), pn = ||phi||^2 ----------------
// grid 2048, 128 threads; 4 rows per block, thread j owns embedding dim j
__global__ void phi_pn_kernel(const float* __restrict__ x,
                              const float* __restrict__ W,
                              const float* __restrict__ bias) {
    __shared__ float xs[4 * DIN];
    __shared__ float pnred[4][4];
    const int tid = threadIdx.x;           // j = tid, 0..127
    const int r0 = blockIdx.x * 4;

    for (int idx = tid; idx < 4 * DIN; idx += 128)
        xs[idx] = x[r0 * DIN + idx];
    const float bj = bias[tid];
    __syncthreads();

    float a0 = 0.f, a1 = 0.f, a2 = 0.f, a3 = 0.f;
    #pragma unroll 8
    for (int k = 0; k < DIN; ++k) {
        float w = W[k * DE + tid];
        a0 += xs[k] * w;
        a1 += xs[DIN + k] * w;
        a2 += xs[2 * DIN + k] * w;
        a3 += xs[3 * DIN + k] * w;
    }
    a0 += bj; a1 += bj; a2 += bj; a3 += bj;

    // phiT rows: 16B store per thread (row j, cols r0..r0+3)
    float4 o = make_float4(-2.f * a0, -2.f * a1, -2.f * a2, -2.f * a3);
    *reinterpret_cast<float4*>(&g_phiT[tid * B_N + r0]) = o;

    // pn block reduction (sum of phi^2 over j)
    const int lane = tid & 31, warp = tid >> 5;
    float s[4] = {a0 * a0, a1 * a1, a2 * a2, a3 * a3};
    #pragma unroll
    for (int r = 0; r < 4; ++r) {
        float v = s[r];
        #pragma unroll
        for (int o2 = 16; o2; o2 >>= 1) v += __shfl_xor_sync(0xffffffffu, v, o2);
        if (lane == 0) pnred[r][warp] = v;
    }
    __syncthreads();
    if (tid < 4)
        g_pn[r0 + tid] = pnred[tid][0] + pnred[tid][1] + pnred[tid][2] + pnred[tid][3];
}

// ---------------- kernel 2: Et = E^T ----------------
__global__ void et_kernel(const float* __restrict__ E) {
    __shared__ float tile[32][33];
    const int nb = blockIdx.x * 32, kb = blockIdx.y * 32;
    const int tx = threadIdx.x, ty = threadIdx.y;
    #pragma unroll
    for (int i = 0; i < 4; ++i)
        tile[ty + i * 8][tx] = E[(nb + ty + i * 8) * DE + kb + tx];
    __syncthreads();
    #pragma unroll
    for (int i = 0; i < 4; ++i)
        g_Et[(kb + ty + i * 8) * NEX + nb + tx] = tile[tx][ty + i * 8];
}

// ---------------- kernel 3: en[n] = ||E_n||^2 ----------------
__global__ void en_kernel(const float* __restrict__ E) {
    const int warp = threadIdx.x >> 5, lane = threadIdx.x & 31;
    const int row = blockIdx.x * 8 + warp;
    const float4* Ev = reinterpret_cast<const float4*>(E);
    float4 v = Ev[row * (DE / 4) + lane];
    float s = v.x * v.x + v.y * v.y + v.z * v.z + v.w * v.w;
    #pragma unroll
    for (int o = 16; o; o >>= 1) s += __shfl_xor_sync(0xffffffffu, s, o);
    if (lane == 0) g_en[row] = s;
}

// ---------------- kernel 4: exemplar KM curves ----------------
// block (64,4): 4 rows per block, 64 durations per row
__global__ void km_kernel(const float* __restrict__ lev,
                          const float* __restrict__ lcen) {
    __shared__ float buf[4][64];
    const int t = threadIdx.x, ty = threadIdx.y;
    const int row = blockIdx.x * 4 + ty;
    float ev = expf(lev[row * NDUR + t]);
    float cn = expf(lcen[row * NDUR + t]);
    float v = ev + cn;
    buf[ty][t] = v;
    // inclusive suffix sum (at_risk)
    #pragma unroll
    for (int off = 1; off < 64; off <<= 1) {
        __syncthreads();
        float add = (t + off < 64) ? buf[ty][t + off] : 0.f;
        __syncthreads();
        v += add;
        buf[ty][t] = v;
    }
    float at_risk = v;
    float hz = (at_risk > 0.f) ? (ev / at_risk) : 0.f;
    float lg = logf(1.f - hz + 1e-7f);
    __syncthreads();
    buf[ty][t] = lg;
    float c = lg;
    // inclusive prefix sum (log-KM)
    #pragma unroll
    for (int off = 1; off < 64; off <<= 1) {
        __syncthreads();
        float add = (t >= off) ? buf[ty][t - off] : 0.f;
        __syncthreads();
        c += add;
        buf[ty][t] = c;
    }
    g_KM[row * NDUR + t] = expf(c);
}

// ---------------- kernel 5: gamma * baseline KM ----------------
__global__ void bh_kernel(const float* __restrict__ lh) {
    if (threadIdx.x == 0 && blockIdx.x == 0) {
        float c = 0.f;
        for (int tt = 0; tt < NDUR; ++tt) {
            float h = 1.f / (1.f + expf(-lh[tt]));
            c += logf(1.f - h + 1e-7f);
            g_gbh[tt] = GAMMA_N * expf(c);
        }
    }
}

// ---------------- kernel 6: fused main kernel ----------------
// grid (64, 2): x = 128-row B tile, y = NE half (8192 exemplars, 128 tiles of 64)
// Thread mapping: mG = tid>>4 (m0=mG*8), nG/dG = tid&15 (n0=nG*4, d0=dG*4)
#define TILE_N 64
#define SM_AS   0        // 16384 floats: phiT tile [k=128][m=128]
#define SM_BS   16384    // 2*8192 floats: E tile db [buf][k=128][n=64]
#define SM_KWS  32768    // 8192 floats: kw tile [m=128][n=64]
#define SM_KMS  40960    // 4096 floats: KM tile [n=64][d=64]
#define SM_ENS  45056    // 64 floats
#define SM_RED  45120    // 2048 floats: denom reduce [16][128]
#define SM_FLOATS 47168

__device__ __forceinline__ void issue_E(float* dst, int nb, int tid) {
    #pragma unroll
    for (int i = 0; i < 8; ++i) {
        int f = tid + i * 256;
        int k = f >> 4, c = f & 15;
        cp_async16(dst + k * TILE_N + c * 4, g_Et + k * NEX + nb + c * 4);
    }
}
__device__ __forceinline__ void issue_KM(float* kms, float* ens, int nb, int tid) {
    #pragma unroll
    for (int i = 0; i < 4; ++i) {
        int f = tid + i * 256;
        int n = f >> 4, c = f & 15;
        cp_async16(kms + n * NDUR + c * 4, g_KM + (nb + n) * NDUR + c * 4);
    }
    if (tid < 16) cp_async16(ens + tid * 4, g_en + nb + tid * 4);
}

extern "C" __global__ void __launch_bounds__(256, 1) main_kernel() {
    extern __shared__ float sm[];
    float* As  = sm + SM_AS;
    float* Bs  = sm + SM_BS;
    float* kws = sm + SM_KWS;
    float* KMs = sm + SM_KMS;
    float* ens = sm + SM_ENS;
    float* red = sm + SM_RED;

    const int tid = threadIdx.x;
    const int bm = blockIdx.x;
    const int split = blockIdx.y;
    const int mG = tid >> 4, lG = tid & 15;
    const int m0 = mG * 8, n0 = lG * 4, d0 = lG * 4;
    const int nsplit0 = split * (NEX / 2);

    // prologue: E(0) in its own group
    issue_E(Bs, nsplit0, tid);
    CP_COMMIT();

    // load phiT tile (plain loads, overlaps with cp.async)
    {
        const float4* src = reinterpret_cast<const float4*>(g_phiT);
        float4* dst = reinterpret_cast<float4*>(As);
        #pragma unroll
        for (int i = 0; i < 16; ++i) {
            int f = tid + i * 256;
            int k = f >> 5, c = f & 31;
            dst[k * 32 + c] = src[k * (B_N / 4) + bm * 32 + c];
        }
    }
    float pnr[8];
    #pragma unroll
    for (int i = 0; i < 8; ++i) pnr[i] = g_pn[bm * 128 + m0 + i];

    float acc2[8][4];
    #pragma unroll
    for (int mi = 0; mi < 8; ++mi)
        #pragma unroll
        for (int di = 0; di < 4; ++di) acc2[mi][di] = 0.f;
    float denomAcc[8];
    #pragma unroll
    for (int mi = 0; mi < 8; ++mi) denomAcc[mi] = 0.f;

    int cur = 0;
    for (int t = 0; t < 128; ++t) {
        const int nb = nsplit0 + t * TILE_N;
        __syncthreads();  // protect KMs/kws/Bs(next) reuse from prior iteration

        issue_KM(KMs, ens, nb, tid);
        CP_COMMIT();
        if (t + 1 < 128) {
            issue_E(Bs + (cur ^ 1) * (DE * TILE_N), nb + TILE_N, tid);
            CP_COMMIT();
            CP_WAIT1();   // all but E(t+1) done: E(t), KM(t), ens(t) ready
        } else {
            CP_WAIT0();
        }
        __syncthreads();

        const float* BsCur = Bs + cur * (DE * TILE_N);

        // ---- GEMM1: S = (-2 phi) . E ----
        float acc1[8][4];
        #pragma unroll
        for (int mi = 0; mi < 8; ++mi)
            #pragma unroll
            for (int ni = 0; ni < 4; ++ni) acc1[mi][ni] = 0.f;

        #pragma unroll 8
        for (int k = 0; k < DE; ++k) {
            float4 a0 = *reinterpret_cast<const float4*>(As + k * 128 + m0);
            float4 a1 = *reinterpret_cast<const float4*>(As + k * 128 + m0 + 4);
            float4 bb = *reinterpret_cast<const float4*>(BsCur + k * TILE_N + n0);
            float am[8] = {a0.x, a0.y, a0.z, a0.w, a1.x, a1.y, a1.z, a1.w};
            float bn[4] = {bb.x, bb.y, bb.z, bb.w};
            #pragma unroll
            for (int mi = 0; mi < 8; ++mi)
                #pragma unroll
                for (int ni = 0; ni < 4; ++ni)
                    acc1[mi][ni] += am[mi] * bn[ni];
        }

        // ---- epilogue: kw = mask * exp(-d2) ----
        #pragma unroll
        for (int mi = 0; mi < 8; ++mi) {
            float4 kv;
            float* kvp = reinterpret_cast<float*>(&kv);
            #pragma unroll
            for (int ni = 0; ni < 4; ++ni) {
                float d2 = pnr[mi] + ens[n0 + ni] + acc1[mi][ni];
                d2 = fmaxf(d2, 0.f);
                float kw = (d2 <= 1.0f) ? __expf(-d2) : 0.f;
                denomAcc[mi] += kw;
                kvp[ni] = kw;
            }
            *reinterpret_cast<float4*>(&kws[(m0 + mi) * TILE_N + n0]) = kv;
        }
        __syncthreads();

        // ---- GEMM2: numer += kw @ KM ----
        #pragma unroll 4
        for (int n = 0; n < TILE_N; ++n) {
            float4 km = *reinterpret_cast<const float4*>(KMs + n * NDUR + d0);
            #pragma unroll
            for (int mi = 0; mi < 8; ++mi) {
                float w = kws[(m0 + mi) * TILE_N + n];
                acc2[mi][0] += w * km.x;
                acc2[mi][1] += w * km.y;
                acc2[mi][2] += w * km.z;
                acc2[mi][3] += w * km.w;
            }
        }
        cur ^= 1;
    }

    // write partial numerators
    #pragma unroll
    for (int mi = 0; mi < 8; ++mi) {
        float4 o = make_float4(acc2[mi][0], acc2[mi][1], acc2[mi][2], acc2[mi][3]);
        *reinterpret_cast<float4*>(
            &g_pnum[(split * B_N + bm * 128 + m0 + mi) * NDUR + d0]) = o;
    }

    // denom reduction across the 16 lG groups
    __syncthreads();
    #pragma unroll
    for (int mi = 0; mi < 8; ++mi) red[lG * 128 + m0 + mi] = denomAcc[mi];
    __syncthreads();
    if (tid < 128) {
        float s = 0.f;
        #pragma unroll
        for (int g = 0; g < 16; ++g) s += red[g * 128 + tid];
        g_pden[split * B_N + bm * 128 + tid] = s;
    }
}

// ---------------- kernel 7: finalize ----------------
__global__ void finalize_kernel(float* __restrict__ out) {
    const int idx = blockIdx.x * 256 + threadIdx.x;  // over B_N*NDUR
    const int b = idx >> 6, d = idx & 63;
    float num = g_pnum[idx] + g_pnum[B_N * NDUR + idx] + g_gbh[d];
    float den = g_pden[b] + g_pden[B_N + b] + GAMMA_N + 1e-12f;
    float r = num / den;
    r = fminf(fmaxf(r, 1e-12f), 1.0f - 1e-12f);
    out[idx] = r;
}

// ---------------- launch ----------------
extern "C" void kernel_launch(void* const* d_in, const int* in_sizes, int n_in,
                              void* d_out, int out_size) {
    const float* x    = (const float*)d_in[0];
    const float* W    = (const float*)d_in[1];
    const float* bias = (const float*)d_in[2];
    const float* E    = (const float*)d_in[3];
    const float* lev  = (const float*)d_in[4];
    const float* lcen = (const float*)d_in[5];
    const float* lh   = (const float*)d_in[6];
    float* out = (float*)d_out;

    static bool attr_set = false;
    if (!attr_set) {
        cudaFuncSetAttribute(main_kernel,
                             cudaFuncAttributeMaxDynamicSharedMemorySize,
                             SM_FLOATS * sizeof(float));
        attr_set = true;
    }

    phi_pn_kernel<<<B_N / 4, 128>>>(x, W, bias);
    et_kernel<<<dim3(NEX / 32, DE / 32), dim3(32, 8)>>>(E);
    en_kernel<<<NEX / 8, 256>>>(E);
    km_kernel<<<NEX / 4, dim3(64, 4)>>>(lev, lcen);
    bh_kernel<<<1, 32>>>(lh);
    main_kernel<<<dim3(B_N / 128, 2), 256, SM_FLOATS * sizeof(float)>>>();
    finalize_kernel<<<(B_N * NDUR) / 256, 256>>>(out);
}